// round 7
// baseline (speedup 1.0000x reference)
#include <cuda_runtime.h>

#define BB 4
#define NCH 3
#define NCLS 20
#define HH 512
#define WW 512
#define MAXB 50
#define THREADS 256
#define TILE_PIX 2048
#define NTILES 32              // 32*2048 = 65536 >= max box area (255*255)
#define NBLK (BB * MAXB * NTILES)

__device__ float g_acc = 0.0f;
__device__ int g_count = 0;

__global__ void sel_fused_kernel(const float* __restrict__ y_fcn,
                                 const float* __restrict__ im_data,
                                 const int* __restrict__ gt_boxes,
                                 const int* __restrict__ num_boxes,
                                 float* __restrict__ out) {
    const int boxid = blockIdx.x;          // 0 .. B*MAXB-1
    const int tile  = blockIdx.y;          // 0 .. NTILES-1
    const int b = boxid / MAXB;
    const int j = boxid % MAXB;
    const int tid = threadIdx.x;
    const int lane = tid & 31;
    const int warp = tid >> 5;

    float a0 = 0.0f, a1 = 0.0f;
    float inv_denom = 0.0f;
    bool work = false;

    int x1 = 0, y1 = 0, wid = 0, start = 0, end = 0;
    const float* im0 = nullptr;
    const float* yf0 = nullptr;

    if (j < num_boxes[b]) {
        const int* g = gt_boxes + (size_t)boxid * 5;
        x1 = g[0];
        y1 = g[1];
        const int x2 = g[2], y2 = g[3], cls = g[4];
        const int hgt = y2 - y1;
        wid = x2 - x1;
        const int area = hgt * wid;
        start = tile * TILE_PIX;
        if (hgt > 0 && wid > 0 && start < area) {
            end = min(start + TILE_PIX, area);
            inv_denom = 1.0f / (float)(NCH * area);
            const size_t plane = (size_t)HH * WW;
            im0 = im_data + (size_t)b * NCH * plane;
            yf0 = y_fcn + ((size_t)b * NCLS + cls) * NCH * plane;
            work = true;
        }
    }

    if (work) {
        const int plane = HH * WW;
#pragma unroll 4
        for (int idx = start + tid; idx < end; idx += THREADS) {
            const int rr = idx / wid;
            const int cc = idx - rr * wid;
            const int off = (y1 + rr) * WW + x1 + cc;
            const float d0 = __ldg(im0 + off)             - __ldg(yf0 + off);
            const float d1 = __ldg(im0 + plane + off)     - __ldg(yf0 + plane + off);
            const float d2 = __ldg(im0 + 2 * plane + off) - __ldg(yf0 + 2 * plane + off);
            a0 += d0 * d0 + d2 * d2;
            a1 += d1 * d1;
        }
    }

    float acc = (a0 + a1) * inv_denom;

    // block reduction
    __shared__ float sm[THREADS / 32];
#pragma unroll
    for (int o = 16; o > 0; o >>= 1)
        acc += __shfl_down_sync(0xffffffffu, acc, o);
    if (lane == 0) sm[warp] = acc;
    __syncthreads();

    __shared__ bool is_last;
    if (tid == 0) {
        float s = 0.0f;
#pragma unroll
        for (int w = 0; w < THREADS / 32; w++) s += sm[w];
        if (s != 0.0f) atomicAdd(&g_acc, s);
        __threadfence();
        const int ticket = atomicAdd(&g_count, 1);
        is_last = (ticket == NBLK - 1);
    }
    __syncthreads();

    if (is_last && tid == 0) {
        const float tot = atomicAdd(&g_acc, 0.0f);  // coherent L2 read
        int nb = 0;
#pragma unroll
        for (int bi = 0; bi < BB; bi++) nb += num_boxes[bi];
        out[0] = tot / (float)nb;
        // reset state for the next graph replay (deterministic per call)
        g_acc = 0.0f;
        g_count = 0;
    }
}

extern "C" void kernel_launch(void* const* d_in, const int* in_sizes, int n_in,
                              void* d_out, int out_size) {
    const float* y_fcn     = (const float*)d_in[0];  // [B, NCH*NCLS, H, W]
    const float* im_data   = (const float*)d_in[1];  // [B, NCH, H, W]
    // d_in[2] = im_info (unused)
    const int*   gt_boxes  = (const int*)d_in[3];    // [B, MAXB, 5]
    const int*   num_boxes = (const int*)d_in[4];    // [B]
    float*       out       = (float*)d_out;

    dim3 grid(BB * MAXB, NTILES);
    sel_fused_kernel<<<grid, THREADS>>>(y_fcn, im_data, gt_boxes, num_boxes, out);
}

// round 9
// speedup vs baseline: 1.1130x; 1.1130x over previous
#include <cuda_runtime.h>

#define BB 4
#define NCH 3
#define NCLS 20
#define HH 512
#define WW 512
#define MAXB 50
#define THREADS 256
#define TILE_PIX 1024
#define NTILES 64              // 64*1024 = 65536 >= max box area (255*255)
#define NBOX (BB * MAXB)
#define NITEMS (NBOX * NTILES)
#define GRID 592               // 148 SMs * 4 CTAs -> exactly one wave

__device__ float g_acc = 0.0f;
__device__ int g_count = 0;

__global__ __launch_bounds__(THREADS, 4)
void sel_persist_kernel(const float* __restrict__ y_fcn,
                        const float* __restrict__ im_data,
                        const int* __restrict__ gt_boxes,
                        const int* __restrict__ num_boxes,
                        float* __restrict__ out) {
    const int tid = threadIdx.x;
    const int lane = tid & 31;
    const int warp = tid >> 5;
    const int plane = HH * WW;

    // hoist per-batch box counts (read once per CTA)
    int nb0 = __ldg(num_boxes + 0);
    int nb1 = __ldg(num_boxes + 1);
    int nb2 = __ldg(num_boxes + 2);
    int nb3 = __ldg(num_boxes + 3);

    float acc = 0.0f;

    for (int item = blockIdx.x; item < NITEMS; item += GRID) {
        const int boxid = item >> 6;        // / NTILES
        const int tile  = item & (NTILES - 1);
        const int b = boxid / MAXB;
        const int j = boxid - b * MAXB;
        const int nb = (b == 0) ? nb0 : (b == 1) ? nb1 : (b == 2) ? nb2 : nb3;
        if (j >= nb) continue;

        const int* g = gt_boxes + boxid * 5;
        const int x1 = __ldg(g), y1 = __ldg(g + 1);
        const int x2 = __ldg(g + 2), y2 = __ldg(g + 3), cls = __ldg(g + 4);
        const int hgt = y2 - y1;
        const int wid = x2 - x1;
        if (hgt <= 0 || wid <= 0) continue;
        const int area = hgt * wid;
        const int start = tile * TILE_PIX;
        if (start >= area) continue;
        const int end = min(start + TILE_PIX, area);

        const float* im0 = im_data + b * NCH * plane;
        const float* yf0 = y_fcn + (b * NCLS + cls) * NCH * plane;
        const float inv_denom = 1.0f / (float)(NCH * area);

        float a0 = 0.0f, a1 = 0.0f;
#pragma unroll 4
        for (int idx = start + tid; idx < end; idx += THREADS) {
            const int rr = idx / wid;
            const int cc = idx - rr * wid;
            const int off = (y1 + rr) * WW + x1 + cc;
            const float d0 = __ldg(im0 + off)             - __ldg(yf0 + off);
            const float d1 = __ldg(im0 + plane + off)     - __ldg(yf0 + plane + off);
            const float d2 = __ldg(im0 + 2 * plane + off) - __ldg(yf0 + 2 * plane + off);
            a0 += d0 * d0 + d2 * d2;
            a1 += d1 * d1;
        }
        acc += (a0 + a1) * inv_denom;
    }

    // block reduction
    __shared__ float sm[THREADS / 32];
#pragma unroll
    for (int o = 16; o > 0; o >>= 1)
        acc += __shfl_down_sync(0xffffffffu, acc, o);
    if (lane == 0) sm[warp] = acc;
    __syncthreads();

    __shared__ bool is_last;
    if (tid == 0) {
        float s = 0.0f;
#pragma unroll
        for (int w = 0; w < THREADS / 32; w++) s += sm[w];
        if (s != 0.0f) atomicAdd(&g_acc, s);
        __threadfence();
        const int ticket = atomicAdd(&g_count, 1);
        is_last = (ticket == GRID - 1);
    }
    __syncthreads();

    if (is_last && tid == 0) {
        const float tot = atomicAdd(&g_acc, 0.0f);  // coherent L2 read
        out[0] = tot / (float)(nb0 + nb1 + nb2 + nb3);
        // reset state for the next graph replay (deterministic per call)
        g_acc = 0.0f;
        g_count = 0;
    }
}

extern "C" void kernel_launch(void* const* d_in, const int* in_sizes, int n_in,
                              void* d_out, int out_size) {
    const float* y_fcn     = (const float*)d_in[0];  // [B, NCH*NCLS, H, W]
    const float* im_data   = (const float*)d_in[1];  // [B, NCH, H, W]
    // d_in[2] = im_info (unused)
    const int*   gt_boxes  = (const int*)d_in[3];    // [B, MAXB, 5]
    const int*   num_boxes = (const int*)d_in[4];    // [B]
    float*       out       = (float*)d_out;

    sel_persist_kernel<<<GRID, THREADS>>>(y_fcn, im_data, gt_boxes, num_boxes, out);
}